// round 6
// baseline (speedup 1.0000x reference)
#include <cuda_runtime.h>

#define NN 50000
#define EE 800000
#define PADX 68   // 17 float4 per row: 16B-aligned rows, bank-shifted

typedef unsigned long long u64;

// persistent scratch (allocation-free rule: __device__ globals)
__device__ float g_xh[NN * 64];
__device__ float g_eh[EE * 64];
__device__ float g_agg[NN * 64];
__device__ float g_P[NN * 64];
__device__ float g_Q[NN * 64];

__device__ __forceinline__ void red_add_v4(float* p, float4 v) {
    asm volatile("red.global.add.v4.f32 [%0], {%1,%2,%3,%4};"
                 :: "l"(p), "f"(v.x), "f"(v.y), "f"(v.z), "f"(v.w) : "memory");
}
// packed fp32x2 FMA (FFMA2): 2 fp32 FMAs per fma-pipe issue slot, exact fp32
__device__ __forceinline__ u64 pk2(float v) {
    u64 r; asm("mov.b64 %0, {%1, %1};" : "=l"(r) : "f"(v)); return r;
}
__device__ __forceinline__ void fma2(u64& d, u64 a, u64 b) {
    asm("fma.rn.f32x2 %0, %1, %2, %3;" : "=l"(d) : "l"(a), "l"(b), "l"(d));
}
__device__ __forceinline__ float2 up2(u64 a) {
    float2 f; asm("mov.b64 {%0, %1}, %2;" : "=f"(f.x), "=f"(f.y) : "l"(a)); return f;
}

// ---------------------------------------------------------------------------
// Encoder: in [M, FIN] -> relu(in@W1+b1)@W2+b2 -> out [M, 64]
// ---------------------------------------------------------------------------
template <int FIN>
__global__ __launch_bounds__(256) void k_encode(
    const float* __restrict__ inp, int M,
    const float* __restrict__ w1, const float* __restrict__ b1,
    const float* __restrict__ w2, const float* __restrict__ b2,
    float* __restrict__ out)
{
    extern __shared__ float sm[];
    float* sW2 = sm;                    // 4096
    float* sW1 = sW2 + 4096;            // FIN*64
    float* sB1 = sW1 + FIN * 64;        // 64
    float* sB2 = sB1 + 64;              // 64
    float* sIn = sB2 + 64;              // 64*FIN
    float* h1  = sIn + 64 * FIN;        // 64*PADX
    for (int i = threadIdx.x; i < 4096; i += 256) sW2[i] = w2[i];
    for (int i = threadIdx.x; i < FIN * 64; i += 256) sW1[i] = w1[i];
    if (threadIdx.x < 64) { sB1[threadIdx.x] = b1[threadIdx.x]; sB2[threadIdx.x] = b2[threadIdx.x]; }
    __syncthreads();
    const int jo = (threadIdx.x & 15) * 4;
    const int eo = (threadIdx.x >> 4) * 4;
    const int ntiles = (M + 63) >> 6;
    for (int t = blockIdx.x; t < ntiles; t += gridDim.x) {
        const int m0 = t << 6;
        for (int idx = threadIdx.x; idx < 64 * FIN; idx += 256) {
            int m = m0 + idx / FIN;
            sIn[idx] = (m < M) ? inp[(size_t)m0 * FIN + idx] : 0.f;
        }
        __syncthreads();
        // layer 1 (tiny K)
        for (int idx = threadIdx.x; idx < 4096; idx += 256) {
            int ml = idx >> 6, j = idx & 63;
            float acc = sB1[j];
#pragma unroll
            for (int k = 0; k < FIN; k++) acc = fmaf(sIn[ml * FIN + k], sW1[k * 64 + j], acc);
            h1[ml * PADX + j] = fmaxf(acc, 0.f);
        }
        __syncthreads();
        // layer 2: 4x4 tile, packed f32x2 FMA
        u64 acc[4][2];
        {
            ulonglong2 bi = *(const ulonglong2*)(sB2 + jo);
#pragma unroll
            for (int i = 0; i < 4; i++) { acc[i][0] = bi.x; acc[i][1] = bi.y; }
        }
        for (int k4 = 0; k4 < 64; k4 += 4) {
            float a[4][4];
#pragma unroll
            for (int i = 0; i < 4; i++)
                *(float4*)a[i] = *(const float4*)(h1 + (eo + i) * PADX + k4);
#pragma unroll
            for (int kk = 0; kk < 4; kk++) {
                ulonglong2 w = *(const ulonglong2*)(sW2 + (k4 + kk) * 64 + jo);
#pragma unroll
                for (int i = 0; i < 4; i++) {
                    u64 av = pk2(a[i][kk]);
                    fma2(acc[i][0], av, w.x);
                    fma2(acc[i][1], av, w.y);
                }
            }
        }
#pragma unroll
        for (int i = 0; i < 4; i++) {
            int m = m0 + eo + i;
            if (m < M) {
                float2 p0 = up2(acc[i][0]), p1 = up2(acc[i][1]);
                *(float4*)(out + (size_t)m * 64 + jo) = make_float4(p0.x, p0.y, p1.x, p1.y);
            }
        }
        __syncthreads();
    }
}

// ---------------------------------------------------------------------------
// P = x_h @ W1b + b1 ; Q = x_h @ W1c
// ---------------------------------------------------------------------------
__global__ __launch_bounds__(256) void k_pq(
    const float* __restrict__ w1b, const float* __restrict__ w1c,
    const float* __restrict__ b1)
{
    extern __shared__ float sm[];
    float* sWb = sm;            // 4096
    float* sWc = sWb + 4096;    // 4096
    float* sB  = sWc + 4096;    // 64
    float* xs  = sB + 64;       // 64*PADX
    for (int i = threadIdx.x; i < 4096; i += 256) { sWb[i] = w1b[i]; sWc[i] = w1c[i]; }
    if (threadIdx.x < 64) sB[threadIdx.x] = b1[threadIdx.x];
    __syncthreads();
    const int jo = (threadIdx.x & 15) * 4;
    const int eo = (threadIdx.x >> 4) * 4;
    const int ntiles = (NN + 63) >> 6;
    for (int t = blockIdx.x; t < ntiles; t += gridDim.x) {
        const int m0 = t << 6;
        for (int idx = threadIdx.x; idx < 1024; idx += 256) {
            int ml = idx >> 4, j4 = (idx & 15) * 4;
            int m = m0 + ml;
            float4 v = (m < NN) ? *(const float4*)(g_xh + (size_t)m * 64 + j4)
                                : make_float4(0.f, 0.f, 0.f, 0.f);
            *(float4*)(xs + ml * PADX + j4) = v;
        }
        __syncthreads();
        u64 ap[4][2], aq[4][2];
        {
            ulonglong2 bi = *(const ulonglong2*)(sB + jo);
#pragma unroll
            for (int i = 0; i < 4; i++) {
                ap[i][0] = bi.x; ap[i][1] = bi.y;
                aq[i][0] = 0ull; aq[i][1] = 0ull;
            }
        }
        for (int k4 = 0; k4 < 64; k4 += 4) {
            float a[4][4];
#pragma unroll
            for (int i = 0; i < 4; i++)
                *(float4*)a[i] = *(const float4*)(xs + (eo + i) * PADX + k4);
#pragma unroll
            for (int kk = 0; kk < 4; kk++) {
                ulonglong2 wb = *(const ulonglong2*)(sWb + (k4 + kk) * 64 + jo);
                ulonglong2 wc = *(const ulonglong2*)(sWc + (k4 + kk) * 64 + jo);
#pragma unroll
                for (int i = 0; i < 4; i++) {
                    u64 av = pk2(a[i][kk]);
                    fma2(ap[i][0], av, wb.x); fma2(ap[i][1], av, wb.y);
                    fma2(aq[i][0], av, wc.x); fma2(aq[i][1], av, wc.y);
                }
            }
        }
#pragma unroll
        for (int i = 0; i < 4; i++) {
            int m = m0 + eo + i;
            if (m < NN) {
                float2 p0 = up2(ap[i][0]), p1 = up2(ap[i][1]);
                float2 q0 = up2(aq[i][0]), q1 = up2(aq[i][1]);
                *(float4*)(g_P + (size_t)m * 64 + jo) = make_float4(p0.x, p0.y, p1.x, p1.y);
                *(float4*)(g_Q + (size_t)m * 64 + jo) = make_float4(q0.x, q0.y, q1.x, q1.y);
            }
        }
        __syncthreads();
    }
}

// ---------------------------------------------------------------------------
// Edge step: h1 = relu(e_h@W1a + P[src] + Q[dst]); e_h += h1@W2 + b2;
//            fused scatter: agg[dst] += e_h_new  (vector red)
// ---------------------------------------------------------------------------
__global__ __launch_bounds__(256, 4) void k_edge(
    const int* __restrict__ src, const int* __restrict__ dst,
    const float* __restrict__ w1a, const float* __restrict__ w2,
    const float* __restrict__ b2)
{
    extern __shared__ float sm[];
    float* sW1 = sm;                    // 4096
    float* sW2 = sW1 + 4096;            // 4096
    float* sB2 = sW2 + 4096;            // 64
    float* ehs = sB2 + 64;              // 64*PADX
    float* h1s = ehs + 64 * PADX;       // 64*PADX
    int*   ssrc = (int*)(h1s + 64 * PADX);  // 64 ints
    int*   sdst = ssrc + 64;                // 64 ints
    for (int i = threadIdx.x; i < 4096; i += 256) { sW1[i] = w1a[i]; sW2[i] = w2[i]; }
    if (threadIdx.x < 64) sB2[threadIdx.x] = b2[threadIdx.x];
    __syncthreads();
    const int jo = (threadIdx.x & 15) * 4;
    const int eo = (threadIdx.x >> 4) * 4;
    const int ntiles = EE >> 6;   // 12500, exact
    for (int t = blockIdx.x; t < ntiles; t += gridDim.x) {
        const int e0 = t << 6;
        if (threadIdx.x < 64) {
            ssrc[threadIdx.x] = src[e0 + threadIdx.x];
            sdst[threadIdx.x] = dst[e0 + threadIdx.x];
        }
        for (int idx = threadIdx.x; idx < 1024; idx += 256) {
            int el = idx >> 4, j4 = (idx & 15) * 4;
            *(float4*)(ehs + el * PADX + j4) =
                *(const float4*)(g_eh + (size_t)(e0 + el) * 64 + j4);
        }
        __syncthreads();
        // GEMM1: e_h @ W1a (packed FMA)
        u64 acc[4][2];
#pragma unroll
        for (int i = 0; i < 4; i++) { acc[i][0] = 0ull; acc[i][1] = 0ull; }
        for (int k4 = 0; k4 < 64; k4 += 4) {
            float a[4][4];
#pragma unroll
            for (int i = 0; i < 4; i++)
                *(float4*)a[i] = *(const float4*)(ehs + (eo + i) * PADX + k4);
#pragma unroll
            for (int kk = 0; kk < 4; kk++) {
                ulonglong2 w = *(const ulonglong2*)(sW1 + (k4 + kk) * 64 + jo);
#pragma unroll
                for (int i = 0; i < 4; i++) {
                    u64 av = pk2(a[i][kk]);
                    fma2(acc[i][0], av, w.x);
                    fma2(acc[i][1], av, w.y);
                }
            }
        }
        // + gathered P[src] + Q[dst], relu -> h1
#pragma unroll
        for (int i = 0; i < 4; i++) {
            int sp = ssrc[eo + i], sd = sdst[eo + i];
            float4 p = *(const float4*)(g_P + (size_t)sp * 64 + jo);
            float4 q = *(const float4*)(g_Q + (size_t)sd * 64 + jo);
            float2 a0 = up2(acc[i][0]), a1 = up2(acc[i][1]);
            *(float4*)(h1s + (eo + i) * PADX + jo) = make_float4(
                fmaxf(a0.x + p.x + q.x, 0.f),
                fmaxf(a0.y + p.y + q.y, 0.f),
                fmaxf(a1.x + p.z + q.z, 0.f),
                fmaxf(a1.y + p.w + q.w, 0.f));
        }
        __syncthreads();
        // GEMM2: h1 @ W2 + b2, residual, store + fused vector scatter-add
        u64 acc2[4][2];
        {
            ulonglong2 bi = *(const ulonglong2*)(sB2 + jo);
#pragma unroll
            for (int i = 0; i < 4; i++) { acc2[i][0] = bi.x; acc2[i][1] = bi.y; }
        }
        for (int k4 = 0; k4 < 64; k4 += 4) {
            float a[4][4];
#pragma unroll
            for (int i = 0; i < 4; i++)
                *(float4*)a[i] = *(const float4*)(h1s + (eo + i) * PADX + k4);
#pragma unroll
            for (int kk = 0; kk < 4; kk++) {
                ulonglong2 w = *(const ulonglong2*)(sW2 + (k4 + kk) * 64 + jo);
#pragma unroll
                for (int i = 0; i < 4; i++) {
                    u64 av = pk2(a[i][kk]);
                    fma2(acc2[i][0], av, w.x);
                    fma2(acc2[i][1], av, w.y);
                }
            }
        }
#pragma unroll
        for (int i = 0; i < 4; i++) {
            int e = e0 + eo + i;
            int sd = sdst[eo + i];
            float4 r = *(const float4*)(ehs + (eo + i) * PADX + jo);
            float2 a0 = up2(acc2[i][0]), a1 = up2(acc2[i][1]);
            float4 v = make_float4(r.x + a0.x, r.y + a0.y, r.z + a1.x, r.w + a1.y);
            *(float4*)(g_eh + (size_t)e * 64 + jo) = v;
            red_add_v4(g_agg + (size_t)sd * 64 + jo, v);
        }
        __syncthreads();
    }
}

// ---------------------------------------------------------------------------
// Node step: x_h += relu(x_h@Wa + agg@Wb + b1)@W2 + b2
// ---------------------------------------------------------------------------
__global__ __launch_bounds__(256) void k_node(
    const float* __restrict__ wa, const float* __restrict__ wb,
    const float* __restrict__ b1, const float* __restrict__ w2,
    const float* __restrict__ b2)
{
    extern __shared__ float sm[];
    float* sWa = sm;                  // 4096
    float* sWb = sWa + 4096;          // 4096
    float* sW2 = sWb + 4096;          // 4096
    float* sB1 = sW2 + 4096;          // 64
    float* sB2 = sB1 + 64;            // 64
    float* xs  = sB2 + 64;            // 64*PADX
    float* as_ = xs + 64 * PADX;      // 64*PADX (agg, then reused for h1)
    for (int i = threadIdx.x; i < 4096; i += 256) { sWa[i] = wa[i]; sWb[i] = wb[i]; sW2[i] = w2[i]; }
    if (threadIdx.x < 64) { sB1[threadIdx.x] = b1[threadIdx.x]; sB2[threadIdx.x] = b2[threadIdx.x]; }
    __syncthreads();
    const int jo = (threadIdx.x & 15) * 4;
    const int eo = (threadIdx.x >> 4) * 4;
    const int ntiles = (NN + 63) >> 6;
    for (int t = blockIdx.x; t < ntiles; t += gridDim.x) {
        const int m0 = t << 6;
        for (int idx = threadIdx.x; idx < 1024; idx += 256) {
            int ml = idx >> 4, j4 = (idx & 15) * 4;
            int m = m0 + ml;
            float4 vx = make_float4(0.f, 0.f, 0.f, 0.f), va = vx;
            if (m < NN) {
                vx = *(const float4*)(g_xh + (size_t)m * 64 + j4);
                va = *(const float4*)(g_agg + (size_t)m * 64 + j4);
            }
            *(float4*)(xs + ml * PADX + j4) = vx;
            *(float4*)(as_ + ml * PADX + j4) = va;
        }
        __syncthreads();
        u64 acc[4][2];
        {
            ulonglong2 bi = *(const ulonglong2*)(sB1 + jo);
#pragma unroll
            for (int i = 0; i < 4; i++) { acc[i][0] = bi.x; acc[i][1] = bi.y; }
        }
        for (int k4 = 0; k4 < 64; k4 += 4) {
            float ax[4][4], aa[4][4];
#pragma unroll
            for (int i = 0; i < 4; i++) {
                *(float4*)ax[i] = *(const float4*)(xs + (eo + i) * PADX + k4);
                *(float4*)aa[i] = *(const float4*)(as_ + (eo + i) * PADX + k4);
            }
#pragma unroll
            for (int kk = 0; kk < 4; kk++) {
                ulonglong2 wA = *(const ulonglong2*)(sWa + (k4 + kk) * 64 + jo);
                ulonglong2 wB = *(const ulonglong2*)(sWb + (k4 + kk) * 64 + jo);
#pragma unroll
                for (int i = 0; i < 4; i++) {
                    u64 avx = pk2(ax[i][kk]);
                    u64 ava = pk2(aa[i][kk]);
                    fma2(acc[i][0], avx, wA.x); fma2(acc[i][1], avx, wA.y);
                    fma2(acc[i][0], ava, wB.x); fma2(acc[i][1], ava, wB.y);
                }
            }
        }
        __syncthreads();   // all GEMM1 reads of as_ done
#pragma unroll
        for (int i = 0; i < 4; i++) {
            float2 a0 = up2(acc[i][0]), a1 = up2(acc[i][1]);
            *(float4*)(as_ + (eo + i) * PADX + jo) = make_float4(
                fmaxf(a0.x, 0.f), fmaxf(a0.y, 0.f), fmaxf(a1.x, 0.f), fmaxf(a1.y, 0.f));
        }
        __syncthreads();
        u64 acc2[4][2];
        {
            ulonglong2 bi = *(const ulonglong2*)(sB2 + jo);
#pragma unroll
            for (int i = 0; i < 4; i++) { acc2[i][0] = bi.x; acc2[i][1] = bi.y; }
        }
        for (int k4 = 0; k4 < 64; k4 += 4) {
            float a[4][4];
#pragma unroll
            for (int i = 0; i < 4; i++)
                *(float4*)a[i] = *(const float4*)(as_ + (eo + i) * PADX + k4);
#pragma unroll
            for (int kk = 0; kk < 4; kk++) {
                ulonglong2 w = *(const ulonglong2*)(sW2 + (k4 + kk) * 64 + jo);
#pragma unroll
                for (int i = 0; i < 4; i++) {
                    u64 av = pk2(a[i][kk]);
                    fma2(acc2[i][0], av, w.x);
                    fma2(acc2[i][1], av, w.y);
                }
            }
        }
#pragma unroll
        for (int i = 0; i < 4; i++) {
            int m = m0 + eo + i;
            if (m < NN) {
                float4 r = *(const float4*)(xs + (eo + i) * PADX + jo);
                float2 a0 = up2(acc2[i][0]), a1 = up2(acc2[i][1]);
                *(float4*)(g_xh + (size_t)m * 64 + jo) = make_float4(
                    r.x + a0.x, r.y + a0.y, r.z + a1.x, r.w + a1.y);
            }
        }
        __syncthreads();
    }
}

// ---------------------------------------------------------------------------
// Decoder: out = relu(x_h@W1+b1)@W2 + b2  -> [N, 6]
// ---------------------------------------------------------------------------
__global__ __launch_bounds__(256) void k_decode(
    const float* __restrict__ w1, const float* __restrict__ b1,
    const float* __restrict__ w2, const float* __restrict__ b2,
    float* __restrict__ out)
{
    extern __shared__ float sm[];
    float* sW1  = sm;                 // 4096
    float* sW2p = sW1 + 4096;         // 64*8 padded
    float* sB1  = sW2p + 512;         // 64
    float* sB2  = sB1 + 64;           // 8
    float* xs   = sB2 + 8;            // 64*PADX
    float* h1s  = xs + 64 * PADX;     // 64*PADX
    for (int i = threadIdx.x; i < 4096; i += 256) sW1[i] = w1[i];
    for (int i = threadIdx.x; i < 64 * 6; i += 256) sW2p[(i / 6) * 8 + (i % 6)] = w2[i];
    if (threadIdx.x < 64) sB1[threadIdx.x] = b1[threadIdx.x];
    if (threadIdx.x < 6) sB2[threadIdx.x] = b2[threadIdx.x];
    __syncthreads();
    const int jo = (threadIdx.x & 15) * 4;
    const int eo = (threadIdx.x >> 4) * 4;
    const int ntiles = (NN + 63) >> 6;
    for (int t = blockIdx.x; t < ntiles; t += gridDim.x) {
        const int m0 = t << 6;
        for (int idx = threadIdx.x; idx < 1024; idx += 256) {
            int ml = idx >> 4, j4 = (idx & 15) * 4;
            int m = m0 + ml;
            float4 v = (m < NN) ? *(const float4*)(g_xh + (size_t)m * 64 + j4)
                                : make_float4(0.f, 0.f, 0.f, 0.f);
            *(float4*)(xs + ml * PADX + j4) = v;
        }
        __syncthreads();
        u64 acc[4][2];
        {
            ulonglong2 bi = *(const ulonglong2*)(sB1 + jo);
#pragma unroll
            for (int i = 0; i < 4; i++) { acc[i][0] = bi.x; acc[i][1] = bi.y; }
        }
        for (int k4 = 0; k4 < 64; k4 += 4) {
            float a[4][4];
#pragma unroll
            for (int i = 0; i < 4; i++)
                *(float4*)a[i] = *(const float4*)(xs + (eo + i) * PADX + k4);
#pragma unroll
            for (int kk = 0; kk < 4; kk++) {
                ulonglong2 w = *(const ulonglong2*)(sW1 + (k4 + kk) * 64 + jo);
#pragma unroll
                for (int i = 0; i < 4; i++) {
                    u64 av = pk2(a[i][kk]);
                    fma2(acc[i][0], av, w.x);
                    fma2(acc[i][1], av, w.y);
                }
            }
        }
#pragma unroll
        for (int i = 0; i < 4; i++) {
            float2 a0 = up2(acc[i][0]), a1 = up2(acc[i][1]);
            *(float4*)(h1s + (eo + i) * PADX + jo) = make_float4(
                fmaxf(a0.x, 0.f), fmaxf(a0.y, 0.f), fmaxf(a1.x, 0.f), fmaxf(a1.y, 0.f));
        }
        __syncthreads();
        for (int idx = threadIdx.x; idx < 64 * 6; idx += 256) {
            int nl = idx / 6, o = idx % 6;
            int m = m0 + nl;
            if (m < NN) {
                float s = sB2[o];
#pragma unroll 8
                for (int k = 0; k < 64; k++) s = fmaf(h1s[nl * PADX + k], sW2p[k * 8 + o], s);
                out[(size_t)m * 6 + o] = s;
            }
        }
        __syncthreads();
    }
}

// ---------------------------------------------------------------------------
extern "C" void kernel_launch(void* const* d_in, const int* in_sizes, int n_in,
                              void* d_out, int out_size)
{
    const float* x         = (const float*)d_in[0];
    const float* edge_attr = (const float*)d_in[1];
    const int*   ei        = (const int*)d_in[2];
    const float* enc_n_w1 = (const float*)d_in[3];
    const float* enc_n_b1 = (const float*)d_in[4];
    const float* enc_n_w2 = (const float*)d_in[5];
    const float* enc_n_b2 = (const float*)d_in[6];
    const float* enc_e_w1 = (const float*)d_in[7];
    const float* enc_e_b1 = (const float*)d_in[8];
    const float* enc_e_w2 = (const float*)d_in[9];
    const float* enc_e_b2 = (const float*)d_in[10];
    const float* pe_w1 = (const float*)d_in[11];
    const float* pe_b1 = (const float*)d_in[12];
    const float* pe_w2 = (const float*)d_in[13];
    const float* pe_b2 = (const float*)d_in[14];
    const float* pn_w1 = (const float*)d_in[15];
    const float* pn_b1 = (const float*)d_in[16];
    const float* pn_w2 = (const float*)d_in[17];
    const float* pn_b2 = (const float*)d_in[18];
    const float* dec_w1 = (const float*)d_in[19];
    const float* dec_b1 = (const float*)d_in[20];
    const float* dec_w2 = (const float*)d_in[21];
    const float* dec_b2 = (const float*)d_in[22];
    float* out = (float*)d_out;

    float *xh_p, *eh_p, *agg_p;
    cudaGetSymbolAddress((void**)&xh_p, g_xh);
    cudaGetSymbolAddress((void**)&eh_p, g_eh);
    cudaGetSymbolAddress((void**)&agg_p, g_agg);

    const int SM_ENC_N = (4096 + 8 * 64 + 128 + 64 * 8 + 64 * PADX) * 4;
    const int SM_ENC_E = (4096 + 4 * 64 + 128 + 64 * 4 + 64 * PADX) * 4;
    const int SM_PQ    = (4096 * 2 + 64 + 64 * PADX) * 4;
    const int SM_EDGE  = (4096 * 2 + 64 + 2 * 64 * PADX + 128) * 4;
    const int SM_NODE  = (4096 * 3 + 128 + 2 * 64 * PADX) * 4;
    const int SM_DEC   = (4096 + 512 + 72 + 2 * 64 * PADX) * 4;

    cudaFuncSetAttribute(k_encode<8>, cudaFuncAttributeMaxDynamicSharedMemorySize, SM_ENC_N);
    cudaFuncSetAttribute(k_encode<4>, cudaFuncAttributeMaxDynamicSharedMemorySize, SM_ENC_E);
    cudaFuncSetAttribute(k_pq,     cudaFuncAttributeMaxDynamicSharedMemorySize, SM_PQ);
    cudaFuncSetAttribute(k_edge,   cudaFuncAttributeMaxDynamicSharedMemorySize, SM_EDGE);
    cudaFuncSetAttribute(k_node,   cudaFuncAttributeMaxDynamicSharedMemorySize, SM_NODE);
    cudaFuncSetAttribute(k_decode, cudaFuncAttributeMaxDynamicSharedMemorySize, SM_DEC);

    const int* src = ei;
    const int* dst = ei + EE;

    // encode
    k_encode<8><<<782, 256, SM_ENC_N>>>(x, NN, enc_n_w1, enc_n_b1, enc_n_w2, enc_n_b2, xh_p);
    k_encode<4><<<888, 256, SM_ENC_E>>>(edge_attr, EE, enc_e_w1, enc_e_b1, enc_e_w2, enc_e_b2, eh_p);

    // process
    for (int l = 0; l < 2; l++) {
        const float* w1a = pe_w1 + l * 192 * 64;
        const float* w1b = w1a + 64 * 64;
        const float* w1c = w1a + 128 * 64;
        cudaMemsetAsync(agg_p, 0, (size_t)NN * 64 * sizeof(float), 0);
        k_pq<<<592, 256, SM_PQ>>>(w1b, w1c, pe_b1 + l * 64);
        k_edge<<<592, 256, SM_EDGE>>>(src, dst, w1a, pe_w2 + l * 64 * 64, pe_b2 + l * 64);
        k_node<<<296, 256, SM_NODE>>>(pn_w1 + l * 128 * 64, pn_w1 + l * 128 * 64 + 64 * 64,
                                      pn_b1 + l * 64, pn_w2 + l * 64 * 64, pn_b2 + l * 64);
    }

    // decode
    k_decode<<<592, 256, SM_DEC>>>(dec_w1, dec_b1, dec_w2, dec_b2, out);
}

// round 7
// speedup vs baseline: 1.7549x; 1.7549x over previous
#include <cuda_runtime.h>

#define NN 50000
#define EE 800000
#define PADX 68   // 17 float4 per row: 16B-aligned rows, bank-shifted

// persistent scratch (allocation-free rule: __device__ globals)
__device__ float g_xh[NN * 64];
__device__ float g_eh[EE * 64];
__device__ float g_agg[NN * 64];
__device__ float g_P[NN * 64];
__device__ float g_Q[NN * 64];

__device__ __forceinline__ void red_add_v4(float* p, float4 v) {
    asm volatile("red.global.add.v4.f32 [%0], {%1,%2,%3,%4};"
                 :: "l"(p), "f"(v.x), "f"(v.y), "f"(v.z), "f"(v.w) : "memory");
}

// ---------------------------------------------------------------------------
// Encoder: in [M, FIN] -> relu(in@W1+b1)@W2+b2 -> out [M, 64]
// ---------------------------------------------------------------------------
template <int FIN>
__global__ __launch_bounds__(256) void k_encode(
    const float* __restrict__ inp, int M,
    const float* __restrict__ w1, const float* __restrict__ b1,
    const float* __restrict__ w2, const float* __restrict__ b2,
    float* __restrict__ out)
{
    extern __shared__ float sm[];
    float* sW2 = sm;                    // 4096
    float* sW1 = sW2 + 4096;            // FIN*64
    float* sB1 = sW1 + FIN * 64;        // 64
    float* sB2 = sB1 + 64;              // 64
    float* sIn = sB2 + 64;              // 64*FIN
    float* h1  = sIn + 64 * FIN;        // 64*PADX
    for (int i = threadIdx.x; i < 4096; i += 256) sW2[i] = w2[i];
    for (int i = threadIdx.x; i < FIN * 64; i += 256) sW1[i] = w1[i];
    if (threadIdx.x < 64) { sB1[threadIdx.x] = b1[threadIdx.x]; sB2[threadIdx.x] = b2[threadIdx.x]; }
    __syncthreads();
    const int jo = (threadIdx.x & 15) * 4;
    const int eo = (threadIdx.x >> 4) * 4;
    const int ntiles = (M + 63) >> 6;
    for (int t = blockIdx.x; t < ntiles; t += gridDim.x) {
        const int m0 = t << 6;
        for (int idx = threadIdx.x; idx < 64 * FIN; idx += 256) {
            int m = m0 + idx / FIN;
            sIn[idx] = (m < M) ? inp[(size_t)m0 * FIN + idx] : 0.f;
        }
        __syncthreads();
        // layer 1 (tiny K)
        for (int idx = threadIdx.x; idx < 4096; idx += 256) {
            int ml = idx >> 6, j = idx & 63;
            float acc = sB1[j];
#pragma unroll
            for (int k = 0; k < FIN; k++) acc = fmaf(sIn[ml * FIN + k], sW1[k * 64 + j], acc);
            h1[ml * PADX + j] = fmaxf(acc, 0.f);
        }
        __syncthreads();
        // layer 2: 4x4 register-tiled 64x64 GEMM, vector A loads
        float acc[4][4];
#pragma unroll
        for (int i = 0; i < 4; i++)
#pragma unroll
            for (int jj = 0; jj < 4; jj++) acc[i][jj] = sB2[jo + jj];
        for (int k4 = 0; k4 < 64; k4 += 4) {
            float a[4][4];
#pragma unroll
            for (int i = 0; i < 4; i++)
                *(float4*)a[i] = *(const float4*)(h1 + (eo + i) * PADX + k4);
#pragma unroll
            for (int kk = 0; kk < 4; kk++) {
                float4 w = *(const float4*)(sW2 + (k4 + kk) * 64 + jo);
#pragma unroll
                for (int i = 0; i < 4; i++) {
                    acc[i][0] = fmaf(a[i][kk], w.x, acc[i][0]);
                    acc[i][1] = fmaf(a[i][kk], w.y, acc[i][1]);
                    acc[i][2] = fmaf(a[i][kk], w.z, acc[i][2]);
                    acc[i][3] = fmaf(a[i][kk], w.w, acc[i][3]);
                }
            }
        }
#pragma unroll
        for (int i = 0; i < 4; i++) {
            int m = m0 + eo + i;
            if (m < M)
                *(float4*)(out + (size_t)m * 64 + jo) = make_float4(acc[i][0], acc[i][1], acc[i][2], acc[i][3]);
        }
        __syncthreads();
    }
}

// ---------------------------------------------------------------------------
// P = x_h @ W1b + b1 ; Q = x_h @ W1c
// ---------------------------------------------------------------------------
__global__ __launch_bounds__(256) void k_pq(
    const float* __restrict__ w1b, const float* __restrict__ w1c,
    const float* __restrict__ b1)
{
    extern __shared__ float sm[];
    float* sWb = sm;            // 4096
    float* sWc = sWb + 4096;    // 4096
    float* sB  = sWc + 4096;    // 64
    float* xs  = sB + 64;       // 64*PADX
    for (int i = threadIdx.x; i < 4096; i += 256) { sWb[i] = w1b[i]; sWc[i] = w1c[i]; }
    if (threadIdx.x < 64) sB[threadIdx.x] = b1[threadIdx.x];
    __syncthreads();
    const int jo = (threadIdx.x & 15) * 4;
    const int eo = (threadIdx.x >> 4) * 4;
    const int ntiles = (NN + 63) >> 6;
    for (int t = blockIdx.x; t < ntiles; t += gridDim.x) {
        const int m0 = t << 6;
        for (int idx = threadIdx.x; idx < 1024; idx += 256) {
            int ml = idx >> 4, j4 = (idx & 15) * 4;
            int m = m0 + ml;
            float4 v = (m < NN) ? *(const float4*)(g_xh + (size_t)m * 64 + j4)
                                : make_float4(0.f, 0.f, 0.f, 0.f);
            *(float4*)(xs + ml * PADX + j4) = v;
        }
        __syncthreads();
        float ap[4][4], aq[4][4];
#pragma unroll
        for (int i = 0; i < 4; i++)
#pragma unroll
            for (int jj = 0; jj < 4; jj++) { ap[i][jj] = sB[jo + jj]; aq[i][jj] = 0.f; }
        for (int k4 = 0; k4 < 64; k4 += 4) {
            float a[4][4];
#pragma unroll
            for (int i = 0; i < 4; i++)
                *(float4*)a[i] = *(const float4*)(xs + (eo + i) * PADX + k4);
#pragma unroll
            for (int kk = 0; kk < 4; kk++) {
                float4 wb = *(const float4*)(sWb + (k4 + kk) * 64 + jo);
                float4 wc = *(const float4*)(sWc + (k4 + kk) * 64 + jo);
#pragma unroll
                for (int i = 0; i < 4; i++) {
                    float v = a[i][kk];
                    ap[i][0] = fmaf(v, wb.x, ap[i][0]); ap[i][1] = fmaf(v, wb.y, ap[i][1]);
                    ap[i][2] = fmaf(v, wb.z, ap[i][2]); ap[i][3] = fmaf(v, wb.w, ap[i][3]);
                    aq[i][0] = fmaf(v, wc.x, aq[i][0]); aq[i][1] = fmaf(v, wc.y, aq[i][1]);
                    aq[i][2] = fmaf(v, wc.z, aq[i][2]); aq[i][3] = fmaf(v, wc.w, aq[i][3]);
                }
            }
        }
#pragma unroll
        for (int i = 0; i < 4; i++) {
            int m = m0 + eo + i;
            if (m < NN) {
                *(float4*)(g_P + (size_t)m * 64 + jo) = make_float4(ap[i][0], ap[i][1], ap[i][2], ap[i][3]);
                *(float4*)(g_Q + (size_t)m * 64 + jo) = make_float4(aq[i][0], aq[i][1], aq[i][2], aq[i][3]);
            }
        }
        __syncthreads();
    }
}

// ---------------------------------------------------------------------------
// Edge step: h1 = relu(e_h@W1a + P[src] + Q[dst]); e_h += h1@W2 + b2;
//            fused scatter: agg[dst] += e_h_new  (vector red)
// Single shared tile buffer (e_h, then reused for h1): 4 blocks/SM.
// ---------------------------------------------------------------------------
__global__ __launch_bounds__(256, 4) void k_edge(
    const int* __restrict__ src, const int* __restrict__ dst,
    const float* __restrict__ w1a, const float* __restrict__ w2,
    const float* __restrict__ b2)
{
    extern __shared__ float sm[];
    float* sW1 = sm;                    // 4096
    float* sW2 = sW1 + 4096;            // 4096
    float* sB2 = sW2 + 4096;            // 64
    float* ebuf = sB2 + 64;             // 64*PADX  (e_h tile, then h1 tile)
    int*   ssrc = (int*)(ebuf + 64 * PADX);  // 64 ints
    int*   sdst = ssrc + 64;                 // 64 ints
    for (int i = threadIdx.x; i < 4096; i += 256) { sW1[i] = w1a[i]; sW2[i] = w2[i]; }
    if (threadIdx.x < 64) sB2[threadIdx.x] = b2[threadIdx.x];
    __syncthreads();
    const int jo = (threadIdx.x & 15) * 4;
    const int eo = (threadIdx.x >> 4) * 4;
    const int ntiles = EE >> 6;   // 12500, exact
    for (int t = blockIdx.x; t < ntiles; t += gridDim.x) {
        const int e0 = t << 6;
        if (threadIdx.x < 64) {
            ssrc[threadIdx.x] = src[e0 + threadIdx.x];
            sdst[threadIdx.x] = dst[e0 + threadIdx.x];
        }
        for (int idx = threadIdx.x; idx < 1024; idx += 256) {
            int el = idx >> 4, j4 = (idx & 15) * 4;
            *(float4*)(ebuf + el * PADX + j4) =
                *(const float4*)(g_eh + (size_t)(e0 + el) * 64 + j4);
        }
        __syncthreads();
        // GEMM1: e_h @ W1a (vector A loads from ebuf)
        float acc[4][4];
#pragma unroll
        for (int i = 0; i < 4; i++)
#pragma unroll
            for (int jj = 0; jj < 4; jj++) acc[i][jj] = 0.f;
        for (int k4 = 0; k4 < 64; k4 += 4) {
            float a[4][4];
#pragma unroll
            for (int i = 0; i < 4; i++)
                *(float4*)a[i] = *(const float4*)(ebuf + (eo + i) * PADX + k4);
#pragma unroll
            for (int kk = 0; kk < 4; kk++) {
                float4 w = *(const float4*)(sW1 + (k4 + kk) * 64 + jo);
#pragma unroll
                for (int i = 0; i < 4; i++) {
                    acc[i][0] = fmaf(a[i][kk], w.x, acc[i][0]);
                    acc[i][1] = fmaf(a[i][kk], w.y, acc[i][1]);
                    acc[i][2] = fmaf(a[i][kk], w.z, acc[i][2]);
                    acc[i][3] = fmaf(a[i][kk], w.w, acc[i][3]);
                }
            }
        }
        // h1 (4x4) in regs: + gathered P[src] + Q[dst], relu
        float4 h1v[4];
#pragma unroll
        for (int i = 0; i < 4; i++) {
            int sp = ssrc[eo + i], sd = sdst[eo + i];
            float4 p = *(const float4*)(g_P + (size_t)sp * 64 + jo);
            float4 q = *(const float4*)(g_Q + (size_t)sd * 64 + jo);
            h1v[i] = make_float4(
                fmaxf(acc[i][0] + p.x + q.x, 0.f),
                fmaxf(acc[i][1] + p.y + q.y, 0.f),
                fmaxf(acc[i][2] + p.z + q.z, 0.f),
                fmaxf(acc[i][3] + p.w + q.w, 0.f));
        }
        // acc2 init = bias + residual (read own e_h block BEFORE ebuf is reused)
        float acc2[4][4];
#pragma unroll
        for (int i = 0; i < 4; i++) {
            float4 r = *(const float4*)(ebuf + (eo + i) * PADX + jo);
            acc2[i][0] = sB2[jo + 0] + r.x;
            acc2[i][1] = sB2[jo + 1] + r.y;
            acc2[i][2] = sB2[jo + 2] + r.z;
            acc2[i][3] = sB2[jo + 3] + r.w;
        }
        __syncthreads();   // all reads of e_h tile done
#pragma unroll
        for (int i = 0; i < 4; i++)
            *(float4*)(ebuf + (eo + i) * PADX + jo) = h1v[i];
        __syncthreads();   // h1 tile ready
        // GEMM2: += h1 @ W2
        for (int k4 = 0; k4 < 64; k4 += 4) {
            float a[4][4];
#pragma unroll
            for (int i = 0; i < 4; i++)
                *(float4*)a[i] = *(const float4*)(ebuf + (eo + i) * PADX + k4);
#pragma unroll
            for (int kk = 0; kk < 4; kk++) {
                float4 w = *(const float4*)(sW2 + (k4 + kk) * 64 + jo);
#pragma unroll
                for (int i = 0; i < 4; i++) {
                    acc2[i][0] = fmaf(a[i][kk], w.x, acc2[i][0]);
                    acc2[i][1] = fmaf(a[i][kk], w.y, acc2[i][1]);
                    acc2[i][2] = fmaf(a[i][kk], w.z, acc2[i][2]);
                    acc2[i][3] = fmaf(a[i][kk], w.w, acc2[i][3]);
                }
            }
        }
#pragma unroll
        for (int i = 0; i < 4; i++) {
            int e = e0 + eo + i;
            int sd = sdst[eo + i];
            float4 v = make_float4(acc2[i][0], acc2[i][1], acc2[i][2], acc2[i][3]);
            *(float4*)(g_eh + (size_t)e * 64 + jo) = v;
            red_add_v4(g_agg + (size_t)sd * 64 + jo, v);
        }
        __syncthreads();
    }
}

// ---------------------------------------------------------------------------
// Node step: x_h += relu(x_h@Wa + agg@Wb + b1)@W2 + b2
// ---------------------------------------------------------------------------
__global__ __launch_bounds__(256) void k_node(
    const float* __restrict__ wa, const float* __restrict__ wb,
    const float* __restrict__ b1, const float* __restrict__ w2,
    const float* __restrict__ b2)
{
    extern __shared__ float sm[];
    float* sWa = sm;                  // 4096
    float* sWb = sWa + 4096;          // 4096
    float* sW2 = sWb + 4096;          // 4096
    float* sB1 = sW2 + 4096;          // 64
    float* sB2 = sB1 + 64;            // 64
    float* xs  = sB2 + 64;            // 64*PADX
    float* as_ = xs + 64 * PADX;      // 64*PADX (agg, then reused for h1)
    for (int i = threadIdx.x; i < 4096; i += 256) { sWa[i] = wa[i]; sWb[i] = wb[i]; sW2[i] = w2[i]; }
    if (threadIdx.x < 64) { sB1[threadIdx.x] = b1[threadIdx.x]; sB2[threadIdx.x] = b2[threadIdx.x]; }
    __syncthreads();
    const int jo = (threadIdx.x & 15) * 4;
    const int eo = (threadIdx.x >> 4) * 4;
    const int ntiles = (NN + 63) >> 6;
    for (int t = blockIdx.x; t < ntiles; t += gridDim.x) {
        const int m0 = t << 6;
        for (int idx = threadIdx.x; idx < 1024; idx += 256) {
            int ml = idx >> 4, j4 = (idx & 15) * 4;
            int m = m0 + ml;
            float4 vx = make_float4(0.f, 0.f, 0.f, 0.f), va = vx;
            if (m < NN) {
                vx = *(const float4*)(g_xh + (size_t)m * 64 + j4);
                va = *(const float4*)(g_agg + (size_t)m * 64 + j4);
            }
            *(float4*)(xs + ml * PADX + j4) = vx;
            *(float4*)(as_ + ml * PADX + j4) = va;
        }
        __syncthreads();
        float acc[4][4];
#pragma unroll
        for (int i = 0; i < 4; i++)
#pragma unroll
            for (int jj = 0; jj < 4; jj++) acc[i][jj] = sB1[jo + jj];
        for (int k4 = 0; k4 < 64; k4 += 4) {
            float ax[4][4], aa[4][4];
#pragma unroll
            for (int i = 0; i < 4; i++) {
                *(float4*)ax[i] = *(const float4*)(xs + (eo + i) * PADX + k4);
                *(float4*)aa[i] = *(const float4*)(as_ + (eo + i) * PADX + k4);
            }
#pragma unroll
            for (int kk = 0; kk < 4; kk++) {
                float4 wAv = *(const float4*)(sWa + (k4 + kk) * 64 + jo);
                float4 wBv = *(const float4*)(sWb + (k4 + kk) * 64 + jo);
#pragma unroll
                for (int i = 0; i < 4; i++) {
                    float vx = ax[i][kk], va = aa[i][kk];
                    acc[i][0] = fmaf(vx, wAv.x, acc[i][0]); acc[i][1] = fmaf(vx, wAv.y, acc[i][1]);
                    acc[i][2] = fmaf(vx, wAv.z, acc[i][2]); acc[i][3] = fmaf(vx, wAv.w, acc[i][3]);
                    acc[i][0] = fmaf(va, wBv.x, acc[i][0]); acc[i][1] = fmaf(va, wBv.y, acc[i][1]);
                    acc[i][2] = fmaf(va, wBv.z, acc[i][2]); acc[i][3] = fmaf(va, wBv.w, acc[i][3]);
                }
            }
        }
        __syncthreads();   // all GEMM1 reads of as_ done
#pragma unroll
        for (int i = 0; i < 4; i++)
            *(float4*)(as_ + (eo + i) * PADX + jo) = make_float4(
                fmaxf(acc[i][0], 0.f), fmaxf(acc[i][1], 0.f),
                fmaxf(acc[i][2], 0.f), fmaxf(acc[i][3], 0.f));
        __syncthreads();
        float acc2[4][4];
#pragma unroll
        for (int i = 0; i < 4; i++)
#pragma unroll
            for (int jj = 0; jj < 4; jj++) acc2[i][jj] = sB2[jo + jj];
        for (int k4 = 0; k4 < 64; k4 += 4) {
            float a[4][4];
#pragma unroll
            for (int i = 0; i < 4; i++)
                *(float4*)a[i] = *(const float4*)(as_ + (eo + i) * PADX + k4);
#pragma unroll
            for (int kk = 0; kk < 4; kk++) {
                float4 w = *(const float4*)(sW2 + (k4 + kk) * 64 + jo);
#pragma unroll
                for (int i = 0; i < 4; i++) {
                    acc2[i][0] = fmaf(a[i][kk], w.x, acc2[i][0]);
                    acc2[i][1] = fmaf(a[i][kk], w.y, acc2[i][1]);
                    acc2[i][2] = fmaf(a[i][kk], w.z, acc2[i][2]);
                    acc2[i][3] = fmaf(a[i][kk], w.w, acc2[i][3]);
                }
            }
        }
#pragma unroll
        for (int i = 0; i < 4; i++) {
            int m = m0 + eo + i;
            if (m < NN) {
                float4 r = *(const float4*)(xs + (eo + i) * PADX + jo);
                *(float4*)(g_xh + (size_t)m * 64 + jo) = make_float4(
                    r.x + acc2[i][0], r.y + acc2[i][1], r.z + acc2[i][2], r.w + acc2[i][3]);
            }
        }
        __syncthreads();
    }
}

// ---------------------------------------------------------------------------
// Decoder: out = relu(x_h@W1+b1)@W2 + b2  -> [N, 6]
// ---------------------------------------------------------------------------
__global__ __launch_bounds__(256) void k_decode(
    const float* __restrict__ w1, const float* __restrict__ b1,
    const float* __restrict__ w2, const float* __restrict__ b2,
    float* __restrict__ out)
{
    extern __shared__ float sm[];
    float* sW1  = sm;                 // 4096
    float* sW2p = sW1 + 4096;         // 64*8 padded
    float* sB1  = sW2p + 512;         // 64
    float* sB2  = sB1 + 64;           // 8
    float* xs   = sB2 + 8;            // 64*PADX
    float* h1s  = xs + 64 * PADX;     // 64*PADX
    for (int i = threadIdx.x; i < 4096; i += 256) sW1[i] = w1[i];
    for (int i = threadIdx.x; i < 64 * 6; i += 256) sW2p[(i / 6) * 8 + (i % 6)] = w2[i];
    if (threadIdx.x < 64) sB1[threadIdx.x] = b1[threadIdx.x];
    if (threadIdx.x < 6) sB2[threadIdx.x] = b2[threadIdx.x];
    __syncthreads();
    const int jo = (threadIdx.x & 15) * 4;
    const int eo = (threadIdx.x >> 4) * 4;
    const int ntiles = (NN + 63) >> 6;
    for (int t = blockIdx.x; t < ntiles; t += gridDim.x) {
        const int m0 = t << 6;
        for (int idx = threadIdx.x; idx < 1024; idx += 256) {
            int ml = idx >> 4, j4 = (idx & 15) * 4;
            int m = m0 + ml;
            float4 v = (m < NN) ? *(const float4*)(g_xh + (size_t)m * 64 + j4)
                                : make_float4(0.f, 0.f, 0.f, 0.f);
            *(float4*)(xs + ml * PADX + j4) = v;
        }
        __syncthreads();
        float acc[4][4];
#pragma unroll
        for (int i = 0; i < 4; i++)
#pragma unroll
            for (int jj = 0; jj < 4; jj++) acc[i][jj] = sB1[jo + jj];
        for (int k4 = 0; k4 < 64; k4 += 4) {
            float a[4][4];
#pragma unroll
            for (int i = 0; i < 4; i++)
                *(float4*)a[i] = *(const float4*)(xs + (eo + i) * PADX + k4);
#pragma unroll
            for (int kk = 0; kk < 4; kk++) {
                float4 w = *(const float4*)(sW1 + (k4 + kk) * 64 + jo);
#pragma unroll
                for (int i = 0; i < 4; i++) {
                    acc[i][0] = fmaf(a[i][kk], w.x, acc[i][0]);
                    acc[i][1] = fmaf(a[i][kk], w.y, acc[i][1]);
                    acc[i][2] = fmaf(a[i][kk], w.z, acc[i][2]);
                    acc[i][3] = fmaf(a[i][kk], w.w, acc[i][3]);
                }
            }
        }
#pragma unroll
        for (int i = 0; i < 4; i++)
            *(float4*)(h1s + (eo + i) * PADX + jo) = make_float4(
                fmaxf(acc[i][0], 0.f), fmaxf(acc[i][1], 0.f),
                fmaxf(acc[i][2], 0.f), fmaxf(acc[i][3], 0.f));
        __syncthreads();
        for (int idx = threadIdx.x; idx < 64 * 6; idx += 256) {
            int nl = idx / 6, o = idx % 6;
            int m = m0 + nl;
            if (m < NN) {
                float s = sB2[o];
#pragma unroll 8
                for (int k = 0; k < 64; k++) s = fmaf(h1s[nl * PADX + k], sW2p[k * 8 + o], s);
                out[(size_t)m * 6 + o] = s;
            }
        }
        __syncthreads();
    }
}

// ---------------------------------------------------------------------------
extern "C" void kernel_launch(void* const* d_in, const int* in_sizes, int n_in,
                              void* d_out, int out_size)
{
    const float* x         = (const float*)d_in[0];
    const float* edge_attr = (const float*)d_in[1];
    const int*   ei        = (const int*)d_in[2];
    const float* enc_n_w1 = (const float*)d_in[3];
    const float* enc_n_b1 = (const float*)d_in[4];
    const float* enc_n_w2 = (const float*)d_in[5];
    const float* enc_n_b2 = (const float*)d_in[6];
    const float* enc_e_w1 = (const float*)d_in[7];
    const float* enc_e_b1 = (const float*)d_in[8];
    const float* enc_e_w2 = (const float*)d_in[9];
    const float* enc_e_b2 = (const float*)d_in[10];
    const float* pe_w1 = (const float*)d_in[11];
    const float* pe_b1 = (const float*)d_in[12];
    const float* pe_w2 = (const float*)d_in[13];
    const float* pe_b2 = (const float*)d_in[14];
    const float* pn_w1 = (const float*)d_in[15];
    const float* pn_b1 = (const float*)d_in[16];
    const float* pn_w2 = (const float*)d_in[17];
    const float* pn_b2 = (const float*)d_in[18];
    const float* dec_w1 = (const float*)d_in[19];
    const float* dec_b1 = (const float*)d_in[20];
    const float* dec_w2 = (const float*)d_in[21];
    const float* dec_b2 = (const float*)d_in[22];
    float* out = (float*)d_out;

    float *xh_p, *eh_p, *agg_p;
    cudaGetSymbolAddress((void**)&xh_p, g_xh);
    cudaGetSymbolAddress((void**)&eh_p, g_eh);
    cudaGetSymbolAddress((void**)&agg_p, g_agg);

    const int SM_ENC_N = (4096 + 8 * 64 + 128 + 64 * 8 + 64 * PADX) * 4;
    const int SM_ENC_E = (4096 + 4 * 64 + 128 + 64 * 4 + 64 * PADX) * 4;
    const int SM_PQ    = (4096 * 2 + 64 + 64 * PADX) * 4;
    const int SM_EDGE  = (4096 * 2 + 64 + 64 * PADX + 128) * 4;   // one tile buffer now
    const int SM_NODE  = (4096 * 3 + 128 + 2 * 64 * PADX) * 4;
    const int SM_DEC   = (4096 + 512 + 72 + 2 * 64 * PADX) * 4;

    cudaFuncSetAttribute(k_encode<8>, cudaFuncAttributeMaxDynamicSharedMemorySize, SM_ENC_N);
    cudaFuncSetAttribute(k_encode<4>, cudaFuncAttributeMaxDynamicSharedMemorySize, SM_ENC_E);
    cudaFuncSetAttribute(k_pq,     cudaFuncAttributeMaxDynamicSharedMemorySize, SM_PQ);
    cudaFuncSetAttribute(k_edge,   cudaFuncAttributeMaxDynamicSharedMemorySize, SM_EDGE);
    cudaFuncSetAttribute(k_node,   cudaFuncAttributeMaxDynamicSharedMemorySize, SM_NODE);
    cudaFuncSetAttribute(k_decode, cudaFuncAttributeMaxDynamicSharedMemorySize, SM_DEC);

    const int* src = ei;
    const int* dst = ei + EE;

    // encode
    k_encode<8><<<782, 256, SM_ENC_N>>>(x, NN, enc_n_w1, enc_n_b1, enc_n_w2, enc_n_b2, xh_p);
    k_encode<4><<<888, 256, SM_ENC_E>>>(edge_attr, EE, enc_e_w1, enc_e_b1, enc_e_w2, enc_e_b2, eh_p);

    // process
    for (int l = 0; l < 2; l++) {
        const float* w1a = pe_w1 + l * 192 * 64;
        const float* w1b = w1a + 64 * 64;
        const float* w1c = w1a + 128 * 64;
        cudaMemsetAsync(agg_p, 0, (size_t)NN * 64 * sizeof(float), 0);
        k_pq<<<592, 256, SM_PQ>>>(w1b, w1c, pe_b1 + l * 64);
        k_edge<<<592, 256, SM_EDGE>>>(src, dst, w1a, pe_w2 + l * 64 * 64, pe_b2 + l * 64);
        k_node<<<296, 256, SM_NODE>>>(pn_w1 + l * 128 * 64, pn_w1 + l * 128 * 64 + 64 * 64,
                                      pn_b1 + l * 64, pn_w2 + l * 64 * 64, pn_b2 + l * 64);
    }

    // decode
    k_decode<<<592, 256, SM_DEC>>>(dec_w1, dec_b1, dec_w2, dec_b2, out);
}